// round 6
// baseline (speedup 1.0000x reference)
#include <cuda_runtime.h>
#include <cuda_fp16.h>
#include <cstdint>

#define OUT_F   4096
#define IN_F    4096
#define M_TOTAL 16384
#define TILE_M  128
#define TILE_N  128
#define TILE_K  32
#define NKTILES (IN_F / TILE_K)          /* 128 */
#define NSTAGE  4
#define NTHREADS 256

/* SMEM rows: 32 halves (64B) padded to 80B (conflict-free ldmatrix) */
#define ROW_BYTES   80
#define A_BYTES     (TILE_M * ROW_BYTES)         /* 10240 */
#define B_BYTES     (TILE_N * ROW_BYTES)         /* 10240 */
#define STAGE_BYTES (A_BYTES + B_BYTES)          /* 20480 */
#define SM_TOTAL    (NSTAGE * STAGE_BYTES)       /* 81920 */

/* fp16 W scratch (x is converted in-loop; no g_Xh pass) */
__device__ __half g_Wh[(size_t)OUT_F * IN_F];        /* 32 MB */

/* ---------------- helpers ---------------- */
__device__ __forceinline__ uint32_t smem_u32(const void* p) {
    uint32_t a;
    asm("{ .reg .u64 t; cvta.to.shared.u64 t, %1; cvt.u32.u64 %0, t; }"
        : "=r"(a) : "l"(p));
    return a;
}
__device__ __forceinline__ void cp16(uint32_t dst, const void* src) {
    asm volatile("cp.async.cg.shared.global [%0], [%1], 16;" :: "r"(dst), "l"(src));
}
__device__ __forceinline__ void ldmatrix_x4(uint32_t* r, uint32_t addr) {
    asm volatile("ldmatrix.sync.aligned.m8n8.x4.shared.b16 {%0,%1,%2,%3}, [%4];"
                 : "=r"(r[0]), "=r"(r[1]), "=r"(r[2]), "=r"(r[3]) : "r"(addr));
}
__device__ __forceinline__ void mma_f16(float* c, const uint32_t* a,
                                        uint32_t b0, uint32_t b1) {
    asm volatile(
        "mma.sync.aligned.m16n8k16.row.col.f32.f16.f16.f32 "
        "{%0,%1,%2,%3}, {%4,%5,%6,%7}, {%8,%9}, {%0,%1,%2,%3};"
        : "+f"(c[0]), "+f"(c[1]), "+f"(c[2]), "+f"(c[3])
        : "r"(a[0]), "r"(a[1]), "r"(a[2]), "r"(a[3]), "r"(b0), "r"(b1));
}
__device__ __forceinline__ uint32_t pack2(float lo, float hi) {
    __half2 h = __floats2half2_rn(lo, hi);
    return *reinterpret_cast<uint32_t*>(&h);
}

/* -------- pass 1: dequant W -> fp16 -------- */
__global__ void __launch_bounds__(256) dequant_kernel(
    const int* __restrict__ Wq, const float* __restrict__ scale,
    const float* __restrict__ zero)
{
    int t = blockIdx.x * 256 + threadIdx.x;
    int e = t << 2;
    int o = e >> 12;
    int i = e & 4095;
    int g = o >> 6;
    int j = ((o & 63) << 12) + i;
    int4   q = *reinterpret_cast<const int4*>(Wq + (size_t)g * 262144 + j);
    float4 s = *reinterpret_cast<const float4*>(scale + j);
    float4 z = *reinterpret_cast<const float4*>(zero + j);
    uint2 pk;
    pk.x = pack2(((float)q.x - z.x) * s.x, ((float)q.y - z.y) * s.y);
    pk.y = pack2(((float)q.z - z.z) * s.z, ((float)q.w - z.w) * s.w);
    *reinterpret_cast<uint2*>(g_Wh + (size_t)o * IN_F + i) = pk;
}

/* -------- pass 2: fp16 GEMM, 128x128x32, fused fp32->fp16 A-loader ------ */
__global__ void __launch_bounds__(NTHREADS, 1)
gemm_kernel(const float* __restrict__ x, const float* __restrict__ bias,
            float* __restrict__ out)
{
    extern __shared__ char smem[];
    const uint32_t sb = smem_u32(smem);
    const int tid  = threadIdx.x;
    const int wid  = tid >> 5, lane = tid & 31;
    const int m0   = blockIdx.y * TILE_M;
    const int n0   = blockIdx.x * TILE_N;
    const int wm   = wid >> 2;          /* 0..1 : 64 M rows */
    const int wn   = wid & 3;           /* 0..3 : 32 N cols */

    /* A loader: 2 threads per row; thread covers 16 fp32 (64B) -> 32B fp16 */
    const int ar = tid >> 1;            /* row 0..127 */
    const int ah = tid & 1;             /* half: floats [16*ah, 16*ah+16) */
    const float*  Asrc   = x + (size_t)(m0 + ar) * IN_F + ah * 16;
    const uint32_t a_sts = (uint32_t)(ar * ROW_BYTES + ah * 32);

    /* B loader: 512 16B-chunks per stage, 2 per thread (cp.async) */
    uint32_t b_dst[2];
    const __half* b_src[2];
    {
        const __half* Wb = g_Wh + (size_t)n0 * IN_F;
#pragma unroll
        for (int j = 0; j < 2; j++) {
            int cid = j * NTHREADS + tid;
            int r = cid >> 2, ch = cid & 3;
            b_dst[j] = (uint32_t)(A_BYTES + r * ROW_BYTES + ch * 16);
            b_src[j] = Wb + (size_t)r * IN_F + ch * 8;
        }
    }

    float4 areg[2][4];                  /* kt-parity double buffer, fp32 */

#define LDGA(KT, P) do {                                                       \
        const float4* _p = reinterpret_cast<const float4*>(Asrc + (KT) * TILE_K); \
        areg[P][0] = _p[0]; areg[P][1] = _p[1];                                \
        areg[P][2] = _p[2]; areg[P][3] = _p[3];                                \
    } while (0)

#define STSA(ST, P) do {                                                       \
        uint32_t _off = (uint32_t)(((ST) & (NSTAGE - 1)) * STAGE_BYTES) + a_sts; \
        uint4 _v0, _v1;                                                        \
        _v0.x = pack2(areg[P][0].x, areg[P][0].y);                             \
        _v0.y = pack2(areg[P][0].z, areg[P][0].w);                             \
        _v0.z = pack2(areg[P][1].x, areg[P][1].y);                             \
        _v0.w = pack2(areg[P][1].z, areg[P][1].w);                             \
        _v1.x = pack2(areg[P][2].x, areg[P][2].y);                             \
        _v1.y = pack2(areg[P][2].z, areg[P][2].w);                             \
        _v1.z = pack2(areg[P][3].x, areg[P][3].y);                             \
        _v1.w = pack2(areg[P][3].z, areg[P][3].w);                             \
        *reinterpret_cast<uint4*>(smem + _off)      = _v0;                     \
        *reinterpret_cast<uint4*>(smem + _off + 16) = _v1;                     \
    } while (0)

#define PREFB(KT) do {                                                         \
        uint32_t _st = sb + (uint32_t)(((KT) & (NSTAGE - 1)) * STAGE_BYTES);   \
        cp16(_st + b_dst[0], b_src[0] + (KT) * TILE_K);                        \
        cp16(_st + b_dst[1], b_src[1] + (KT) * TILE_K);                        \
        asm volatile("cp.async.commit_group;" ::: "memory");                   \
    } while (0)

    /* prologue: B(0..2) async; A(0),A(1) converted to smem; A(2),A(3) in regs */
    PREFB(0); PREFB(1); PREFB(2);
    LDGA(0, 0); STSA(0, 0);
    LDGA(1, 1); STSA(1, 1);
    LDGA(2, 0);
    LDGA(3, 1);

    float acc[4][4][4];
#pragma unroll
    for (int a = 0; a < 4; a++)
#pragma unroll
        for (int b = 0; b < 4; b++)
#pragma unroll
            for (int c = 0; c < 4; c++) acc[a][b][c] = 0.f;

    const uint32_t a_row = (uint32_t)(wm * 64 + (lane & 15));
    const uint32_t b_row = (uint32_t)(wn * 32 + (lane & 15));
    const uint32_t hi    = (uint32_t)(lane >> 4);

    for (int kt = 0; kt < NKTILES; kt++) {
        if (kt < NKTILES - 2)
            asm volatile("cp.async.wait_group 2;" ::: "memory");
        else if (kt == NKTILES - 2)
            asm volatile("cp.async.wait_group 1;" ::: "memory");
        else
            asm volatile("cp.async.wait_group 0;" ::: "memory");
        __syncthreads();

        /* loaders first: keep memory moving under the MMA work */
        if (kt + 3 < NKTILES) PREFB(kt + 3);
        if (kt + 2 < NKTILES) STSA(kt + 2, kt & 1);   /* regs loaded at kt-2 */
        if (kt + 4 < NKTILES) LDGA(kt + 4, kt & 1);

        const uint32_t st = sb + (uint32_t)((kt & (NSTAGE - 1)) * STAGE_BYTES);
#pragma unroll
        for (int ks = 0; ks < 2; ks++) {
            const uint32_t ch = (uint32_t)(ks * 2) + hi;
            uint32_t afr[4][4], bfr[2][4];
#pragma unroll
            for (int mt = 0; mt < 4; mt++)
                ldmatrix_x4(afr[mt],
                            st + (a_row + mt * 16) * ROW_BYTES + ch * 16);
#pragma unroll
            for (int nt2 = 0; nt2 < 2; nt2++)
                ldmatrix_x4(bfr[nt2],
                            st + A_BYTES + (b_row + nt2 * 16) * ROW_BYTES + ch * 16);
#pragma unroll
            for (int mt = 0; mt < 4; mt++)
#pragma unroll
                for (int nt = 0; nt < 4; nt++)
                    mma_f16(acc[mt][nt], afr[mt],
                            bfr[nt >> 1][(nt & 1)], bfr[nt >> 1][(nt & 1) + 2]);
        }
    }

    /* epilogue */
    const int rbase = lane >> 2;
    const int cbase = (lane & 3) * 2;
#pragma unroll
    for (int mt = 0; mt < 4; mt++) {
        const int m = m0 + wm * 64 + mt * 16 + rbase;
#pragma unroll
        for (int nt = 0; nt < 4; nt++) {
            const int n = n0 + wn * 32 + nt * 8 + cbase;
            float2 bv = *reinterpret_cast<const float2*>(bias + n);
            float2 v0, v1;
            v0.x = acc[mt][nt][0] + bv.x;
            v0.y = acc[mt][nt][1] + bv.y;
            v1.x = acc[mt][nt][2] + bv.x;
            v1.y = acc[mt][nt][3] + bv.y;
            *reinterpret_cast<float2*>(out + (size_t)m * OUT_F + n)       = v0;
            *reinterpret_cast<float2*>(out + (size_t)(m + 8) * OUT_F + n) = v1;
        }
    }
}

/* ---------------- launch ---------------- */
extern "C" void kernel_launch(void* const* d_in, const int* in_sizes, int n_in,
                              void* d_out, int out_size)
{
    const float* x     = (const float*)d_in[0];
    const int*   Wq    = (const int*)  d_in[1];
    const float* scale = (const float*)d_in[2];
    const float* zero  = (const float*)d_in[3];
    const float* bias  = (const float*)d_in[4];
    float*       out   = (float*)d_out;

    dequant_kernel<<<(OUT_F * IN_F / 4) / 256, 256>>>(Wq, scale, zero);

    cudaFuncSetAttribute(gemm_kernel,
                         cudaFuncAttributeMaxDynamicSharedMemorySize, SM_TOTAL);
    dim3 grid(OUT_F / TILE_N, M_TOTAL / TILE_M);     /* (32, 128) x-fastest */
    gemm_kernel<<<grid, NTHREADS, SM_TOTAL>>>(x, bias, out);
}

// round 9
// speedup vs baseline: 1.4631x; 1.4631x over previous
#include <cuda_runtime.h>
#include <cuda_fp16.h>
#include <cstdint>

#define OUT_F   4096
#define IN_F    4096
#define M_TOTAL 16384
#define TILE_M  128
#define TILE_N  128
#define TILE_K  32
#define NKTILES (IN_F / TILE_K)          /* 128 */
#define NSTAGE  3
#define NTHREADS 256

/* SMEM rows: 32 halves (64B) padded to 80B (conflict-free ldmatrix) */
#define ROW_BYTES   80
#define A_BYTES     (TILE_M * ROW_BYTES)         /* 10240 */
#define B_BYTES     (TILE_N * ROW_BYTES)         /* 10240 */
#define STAGE_BYTES (A_BYTES + B_BYTES)          /* 20480 */
#define SM_TOTAL    (NSTAGE * STAGE_BYTES)       /* 61440: 2 CTAs/SM fit */

/* fp16 operand scratch */
__device__ __half g_Wh[(size_t)OUT_F * IN_F];        /*  32 MB */
__device__ __half g_Xh[(size_t)M_TOTAL * IN_F];      /* 128 MB */

/* ---------------- helpers ---------------- */
__device__ __forceinline__ uint32_t smem_u32(const void* p) {
    uint32_t a;
    asm("{ .reg .u64 t; cvta.to.shared.u64 t, %1; cvt.u32.u64 %0, t; }"
        : "=r"(a) : "l"(p));
    return a;
}
__device__ __forceinline__ void cp16(uint32_t dst, const void* src) {
    asm volatile("cp.async.cg.shared.global [%0], [%1], 16;" :: "r"(dst), "l"(src));
}
__device__ __forceinline__ void ldmatrix_x4(uint32_t* r, uint32_t addr) {
    asm volatile("ldmatrix.sync.aligned.m8n8.x4.shared.b16 {%0,%1,%2,%3}, [%4];"
                 : "=r"(r[0]), "=r"(r[1]), "=r"(r[2]), "=r"(r[3]) : "r"(addr));
}
__device__ __forceinline__ void mma_f16(float* c, const uint32_t* a,
                                        uint32_t b0, uint32_t b1) {
    asm volatile(
        "mma.sync.aligned.m16n8k16.row.col.f32.f16.f16.f32 "
        "{%0,%1,%2,%3}, {%4,%5,%6,%7}, {%8,%9}, {%0,%1,%2,%3};"
        : "+f"(c[0]), "+f"(c[1]), "+f"(c[2]), "+f"(c[3])
        : "r"(a[0]), "r"(a[1]), "r"(a[2]), "r"(a[3]), "r"(b0), "r"(b1));
}
__device__ __forceinline__ uint32_t pack2(float lo, float hi) {
    __half2 h = __floats2half2_rn(lo, hi);
    return *reinterpret_cast<uint32_t*>(&h);
}

/* -------- pass 1: dequant W -> fp16 -------- */
__global__ void __launch_bounds__(256) dequant_kernel(
    const int* __restrict__ Wq, const float* __restrict__ scale,
    const float* __restrict__ zero)
{
    int t = blockIdx.x * 256 + threadIdx.x;
    int e = t << 2;
    int o = e >> 12;
    int i = e & 4095;
    int g = o >> 6;
    int j = ((o & 63) << 12) + i;
    int4   q = *reinterpret_cast<const int4*>(Wq + (size_t)g * 262144 + j);
    float4 s = *reinterpret_cast<const float4*>(scale + j);
    float4 z = *reinterpret_cast<const float4*>(zero + j);
    uint2 pk;
    pk.x = pack2(((float)q.x - z.x) * s.x, ((float)q.y - z.y) * s.y);
    pk.y = pack2(((float)q.z - z.z) * s.z, ((float)q.w - z.w) * s.w);
    *reinterpret_cast<uint2*>(g_Wh + (size_t)o * IN_F + i) = pk;
}

/* -------- pass 2: x -> fp16 -------- */
__global__ void __launch_bounds__(256) xconv_kernel(const float* __restrict__ x)
{
    size_t t = (size_t)blockIdx.x * 256 + threadIdx.x;
    float4 v = reinterpret_cast<const float4*>(x)[t];
    uint2 pk;
    pk.x = pack2(v.x, v.y);
    pk.y = pack2(v.z, v.w);
    reinterpret_cast<uint2*>(g_Xh)[t] = pk;
}

/* -------- pass 3: fp16 GEMM, 128x128x32, 3-stage, 2 CTAs/SM -------- */
__global__ void __launch_bounds__(NTHREADS, 2)
gemm_kernel(const float* __restrict__ bias, float* __restrict__ out)
{
    extern __shared__ char smem[];
    const uint32_t sb = smem_u32(smem);
    const int tid  = threadIdx.x;
    const int wid  = tid >> 5, lane = tid & 31;
    const int m0   = blockIdx.y * TILE_M;
    const int n0   = blockIdx.x * TILE_N;
    const int wm   = wid >> 2;          /* 0..1 : 64 M rows */
    const int wn   = wid & 3;           /* 0..3 : 32 N cols */

    /* loaders: 1024 16B-chunks per stage (A:512, B:512), 4 per thread */
    const int ld_row = tid >> 1;                 /* 0..127 */
    const int ld_ch2 = (tid & 1) * 2;            /* chunks {0,1} or {2,3} */
    const uint32_t a_off = (uint32_t)(ld_row * ROW_BYTES + ld_ch2 * 16);
    const __half* Asrc = g_Xh + (size_t)(m0 + ld_row) * IN_F + ld_ch2 * 8;
    const __half* Bsrc = g_Wh + (size_t)(n0 + ld_row) * IN_F + ld_ch2 * 8;

#define PREFETCH(KT) do {                                                      \
        int _kt = (KT);                                                        \
        uint32_t _st = sb + (uint32_t)((_kt % NSTAGE) * STAGE_BYTES);          \
        const __half* _a = Asrc + _kt * TILE_K;                                \
        const __half* _b = Bsrc + _kt * TILE_K;                                \
        cp16(_st + a_off,                 _a);                                 \
        cp16(_st + a_off + 16,            _a + 8);                             \
        cp16(_st + A_BYTES + a_off,       _b);                                 \
        cp16(_st + A_BYTES + a_off + 16,  _b + 8);                             \
        asm volatile("cp.async.commit_group;" ::: "memory");                   \
    } while (0)

    PREFETCH(0); PREFETCH(1);

    float acc[4][4][4];
#pragma unroll
    for (int a = 0; a < 4; a++)
#pragma unroll
        for (int b = 0; b < 4; b++)
#pragma unroll
            for (int c = 0; c < 4; c++) acc[a][b][c] = 0.f;

    const uint32_t a_row = (uint32_t)(wm * 64 + (lane & 15));
    const uint32_t b_row = (uint32_t)(wn * 32 + (lane & 15));
    const uint32_t hi    = (uint32_t)(lane >> 4);

    for (int kt = 0; kt < NKTILES; kt++) {
        if (kt < NKTILES - 1)
            asm volatile("cp.async.wait_group 1;" ::: "memory");
        else
            asm volatile("cp.async.wait_group 0;" ::: "memory");
        __syncthreads();

        if (kt + 2 < NKTILES) PREFETCH(kt + 2);

        const uint32_t st = sb + (uint32_t)((kt % NSTAGE) * STAGE_BYTES);
#pragma unroll
        for (int ks = 0; ks < 2; ks++) {
            const uint32_t ch = (uint32_t)(ks * 2) + hi;
            uint32_t afr[4][4], bfr[2][4];
#pragma unroll
            for (int mt = 0; mt < 4; mt++)
                ldmatrix_x4(afr[mt],
                            st + (a_row + mt * 16) * ROW_BYTES + ch * 16);
#pragma unroll
            for (int nt2 = 0; nt2 < 2; nt2++)
                ldmatrix_x4(bfr[nt2],
                            st + A_BYTES + (b_row + nt2 * 16) * ROW_BYTES + ch * 16);
#pragma unroll
            for (int mt = 0; mt < 4; mt++)
#pragma unroll
                for (int nt = 0; nt < 4; nt++)
                    mma_f16(acc[mt][nt], afr[mt],
                            bfr[nt >> 1][(nt & 1)], bfr[nt >> 1][(nt & 1) + 2]);
        }
    }

    /* epilogue */
    const int rbase = lane >> 2;
    const int cbase = (lane & 3) * 2;
#pragma unroll
    for (int mt = 0; mt < 4; mt++) {
        const int m = m0 + wm * 64 + mt * 16 + rbase;
#pragma unroll
        for (int nt = 0; nt < 4; nt++) {
            const int n = n0 + wn * 32 + nt * 8 + cbase;
            float2 bv = *reinterpret_cast<const float2*>(bias + n);
            float2 v0, v1;
            v0.x = acc[mt][nt][0] + bv.x;
            v0.y = acc[mt][nt][1] + bv.y;
            v1.x = acc[mt][nt][2] + bv.x;
            v1.y = acc[mt][nt][3] + bv.y;
            *reinterpret_cast<float2*>(out + (size_t)m * OUT_F + n)       = v0;
            *reinterpret_cast<float2*>(out + (size_t)(m + 8) * OUT_F + n) = v1;
        }
    }
}

/* ---------------- launch ---------------- */
extern "C" void kernel_launch(void* const* d_in, const int* in_sizes, int n_in,
                              void* d_out, int out_size)
{
    const float* x     = (const float*)d_in[0];
    const int*   Wq    = (const int*)  d_in[1];
    const float* scale = (const float*)d_in[2];
    const float* zero  = (const float*)d_in[3];
    const float* bias  = (const float*)d_in[4];
    float*       out   = (float*)d_out;

    dequant_kernel<<<(OUT_F * IN_F / 4) / 256, 256>>>(Wq, scale, zero);
    xconv_kernel<<<(M_TOTAL * IN_F / 4) / 256, 256>>>(x);

    cudaFuncSetAttribute(gemm_kernel,
                         cudaFuncAttributeMaxDynamicSharedMemorySize, SM_TOTAL);
    dim3 grid(OUT_F / TILE_N, M_TOTAL / TILE_M);     /* (32, 128) x-fastest */
    gemm_kernel<<<grid, NTHREADS, SM_TOTAL>>>(bias, out);
}